// round 3
// baseline (speedup 1.0000x reference)
#include <cuda_runtime.h>

#define N_NODES  100000
#define N_EDGES  2000000
#define N_GRAPHS 1000
#define DIM      32
#define NF       7

#define SCAN_CHUNK 512
#define NCHUNKS ((N_NODES + SCAN_CHUNK - 1) / SCAN_CHUNK)   // 196

// ---- device scratch (static; 16B-aligned for float4 paths) ----
__device__ __align__(16) float d_h0[N_NODES * DIM];
__device__ __align__(16) float d_h1[N_NODES * DIM];
__device__ __align__(16) float d_xp[N_NODES * 8];      // padded 8-dim input
__device__ __align__(16) float d_pool[N_GRAPHS * DIM];
__device__ int d_deg[N_NODES];
__device__ int d_incl[N_NODES];          // inclusive scan (per-chunk)
__device__ int d_bsum[NCHUNKS];
__device__ int d_boff[NCHUNKS];
__device__ int d_off[N_NODES + 1];       // CSR row offsets (by dst)
__device__ int d_pos[N_NODES];           // running insert positions
__device__ int d_csr[N_EDGES];           // src node ids grouped by dst

// ---------------------------------------------------------------------------
// prep: pad x -> xp, zero deg + pool
__global__ void prep_x(const float* __restrict__ x) {
    int i = blockIdx.x * blockDim.x + threadIdx.x;
    if (i < N_NODES * 8) {
        int n = i >> 3, j = i & 7;
        d_xp[i] = (j < NF) ? x[n * NF + j] : 0.0f;
        if (i < N_NODES) d_deg[i] = 0;
        if (i < N_GRAPHS * DIM) d_pool[i] = 0.0f;
    }
}

// histogram of dst degrees
__global__ void hist(const int* __restrict__ ei) {
    int e = blockIdx.x * blockDim.x + threadIdx.x;
    if (e < N_EDGES) atomicAdd(&d_deg[ei[N_EDGES + e]], 1);
}

// block-level inclusive scan over 512-chunks
__global__ void scanA() {
    __shared__ int sh[SCAN_CHUNK];
    int i = blockIdx.x * SCAN_CHUNK + threadIdx.x;
    int v = (i < N_NODES) ? d_deg[i] : 0;
    sh[threadIdx.x] = v;
    __syncthreads();
#pragma unroll
    for (int off = 1; off < SCAN_CHUNK; off <<= 1) {
        int t = (threadIdx.x >= off) ? sh[threadIdx.x - off] : 0;
        __syncthreads();
        sh[threadIdx.x] += t;
        __syncthreads();
    }
    if (i < N_NODES) d_incl[i] = sh[threadIdx.x];
    if (threadIdx.x == SCAN_CHUNK - 1) d_bsum[blockIdx.x] = sh[threadIdx.x];
}

// scan of chunk sums (1 block, 256 threads; NCHUNKS=196 <= 256)
__global__ void scanB() {
    __shared__ int sh[256];
    int v = (threadIdx.x < NCHUNKS) ? d_bsum[threadIdx.x] : 0;
    sh[threadIdx.x] = v;
    __syncthreads();
#pragma unroll
    for (int off = 1; off < 256; off <<= 1) {
        int t = (threadIdx.x >= off) ? sh[threadIdx.x - off] : 0;
        __syncthreads();
        sh[threadIdx.x] += t;
        __syncthreads();
    }
    if (threadIdx.x < NCHUNKS) d_boff[threadIdx.x] = sh[threadIdx.x] - v; // exclusive
}

// finalize exclusive offsets + init insert positions
__global__ void scanC() {
    int i = blockIdx.x * blockDim.x + threadIdx.x;
    if (i < N_NODES) {
        int excl = d_incl[i] - d_deg[i] + d_boff[i / SCAN_CHUNK];
        d_off[i] = excl;
        d_pos[i] = excl;
    }
    if (i == 0) d_off[N_NODES] = N_EDGES;
}

// place src ids into CSR slots grouped by dst
__global__ void place(const int* __restrict__ ei) {
    int e = blockIdx.x * blockDim.x + threadIdx.x;
    if (e < N_EDGES) {
        int s = ei[e], d = ei[N_EDGES + e];
        int p = atomicAdd(&d_pos[d], 1);
        d_csr[p] = s;
    }
}

// ---------------------------------------------------------------------------
// Fused layer 1: gather (8-dim, 4 neighbors in parallel per warp) + MLP + BN.
// One warp per node, grid-stride; weights in registers (column `lane`).
__global__ void __launch_bounds__(256)
gin1(const float* __restrict__ W1, const float* __restrict__ b1,
     const float* __restrict__ W2, const float* __restrict__ b2,
     const float* __restrict__ gamma, const float* __restrict__ beta,
     const float* __restrict__ mean, const float* __restrict__ var) {
    int lane = threadIdx.x & 31;
    int j = lane & 7, q = lane >> 3;

    float w1[NF], w2[32];
#pragma unroll
    for (int k = 0; k < NF; k++) w1[k] = W1[k * 32 + lane];
#pragma unroll
    for (int k = 0; k < 32; k++) w2[k] = W2[k * 32 + lane];
    float b1v = b1[lane], b2v = b2[lane];
    float sc = gamma[lane] * rsqrtf(var[lane] + 1e-5f);
    float sh = beta[lane] - mean[lane] * sc;

    int warpId = (blockIdx.x * blockDim.x + threadIdx.x) >> 5;
    int numWarps = (gridDim.x * blockDim.x) >> 5;

    for (int n = warpId; n < N_NODES; n += numWarps) {
        int beg = d_off[n], end = d_off[n + 1];
        float zp = 0.0f;
        for (int e = beg + q; e < end; e += 4)
            zp += d_xp[d_csr[e] * 8 + j];
        zp += __shfl_xor_sync(0xffffffffu, zp, 8);
        zp += __shfl_xor_sync(0xffffffffu, zp, 16);
        float z = d_xp[n * 8 + j] + zp;

        float a = b1v;
#pragma unroll
        for (int k = 0; k < NF; k++)
            a = fmaf(__shfl_sync(0xffffffffu, z, k), w1[k], a);
        a = fmaxf(a, 0.0f);

        float o = b2v;
#pragma unroll
        for (int k = 0; k < 32; k++)
            o = fmaf(__shfl_sync(0xffffffffu, a, k), w2[k], o);
        o = fmaxf(o, 0.0f);

        d_h0[n * DIM + lane] = o * sc + sh;
    }
}

// Fused layers 2..5: 32-dim gather (4-way unrolled) + MLP + BN.
__global__ void __launch_bounds__(256)
gin_layer(const float* __restrict__ hin, float* __restrict__ hout,
          const float* __restrict__ W1, const float* __restrict__ b1,
          const float* __restrict__ W2, const float* __restrict__ b2,
          const float* __restrict__ gamma, const float* __restrict__ beta,
          const float* __restrict__ mean, const float* __restrict__ var) {
    int lane = threadIdx.x & 31;

    float w1[32], w2[32];
#pragma unroll
    for (int k = 0; k < 32; k++) { w1[k] = W1[k * 32 + lane]; w2[k] = W2[k * 32 + lane]; }
    float b1v = b1[lane], b2v = b2[lane];
    float sc = gamma[lane] * rsqrtf(var[lane] + 1e-5f);
    float sh = beta[lane] - mean[lane] * sc;

    int warpId = (blockIdx.x * blockDim.x + threadIdx.x) >> 5;
    int numWarps = (gridDim.x * blockDim.x) >> 5;

    for (int n = warpId; n < N_NODES; n += numWarps) {
        int beg = d_off[n], end = d_off[n + 1];
        float z = hin[n * DIM + lane];
        float z1 = 0.0f, z2 = 0.0f, z3 = 0.0f;
        int e = beg;
        for (; e + 4 <= end; e += 4) {
            int s0 = d_csr[e], s1 = d_csr[e + 1], s2 = d_csr[e + 2], s3 = d_csr[e + 3];
            z  += hin[s0 * DIM + lane];
            z1 += hin[s1 * DIM + lane];
            z2 += hin[s2 * DIM + lane];
            z3 += hin[s3 * DIM + lane];
        }
        for (; e < end; e++) z += hin[d_csr[e] * DIM + lane];
        z += (z1 + z2) + z3;

        float a = b1v;
#pragma unroll
        for (int k = 0; k < 32; k++)
            a = fmaf(__shfl_sync(0xffffffffu, z, k), w1[k], a);
        a = fmaxf(a, 0.0f);

        float o = b2v;
#pragma unroll
        for (int k = 0; k < 32; k++)
            o = fmaf(__shfl_sync(0xffffffffu, a, k), w2[k], o);
        o = fmaxf(o, 0.0f);

        hout[n * DIM + lane] = o * sc + sh;
    }
}

// ---------------------------------------------------------------------------
__device__ __forceinline__ void red_add_v4(float* a, float4 v) {
    asm volatile("red.global.add.v4.f32 [%0], {%1,%2,%3,%4};"
                 :: "l"(a), "f"(v.x), "f"(v.y), "f"(v.z), "f"(v.w)
                 : "memory");
}

// global add pool from d_h0
__global__ void pool_scatter(const int* __restrict__ batch) {
    int t = blockIdx.x * blockDim.x + threadIdx.x;
    if (t >= N_NODES * 8) return;
    int n = t >> 3, p = t & 7;
    int g = batch[n];
    float4 v = *reinterpret_cast<const float4*>(&d_h0[n * DIM + p * 4]);
    red_add_v4(&d_pool[g * DIM + p * 4], v);
}

// head: fc1 + relu + fc2 + log_softmax; one warp per graph
__global__ void head(const float* __restrict__ fc1W, const float* __restrict__ fc1b,
                     const float* __restrict__ fc2W, const float* __restrict__ fc2b,
                     float* __restrict__ out) {
    __shared__ float W1s[32 * 32], W2s[64], b1s[32], b2s[2];
    int tid = threadIdx.x;
    for (int i = tid; i < 32 * 32; i += blockDim.x) W1s[i] = fc1W[i];
    if (tid < 64) W2s[tid] = fc2W[tid];
    if (tid < 32) b1s[tid] = fc1b[tid];
    if (tid < 2)  b2s[tid] = fc2b[tid];
    __syncthreads();

    int warp = tid >> 5, j = tid & 31;
    int g = blockIdx.x * (blockDim.x >> 5) + warp;
    if (g >= N_GRAPHS) return;

    float gj = d_pool[g * DIM + j];
    float a = b1s[j];
#pragma unroll
    for (int k = 0; k < 32; k++)
        a = fmaf(__shfl_sync(0xffffffffu, gj, k), W1s[k * 32 + j], a);
    a = fmaxf(a, 0.0f);

    float p0 = a * W2s[j * 2 + 0];
    float p1 = a * W2s[j * 2 + 1];
#pragma unroll
    for (int off = 16; off > 0; off >>= 1) {
        p0 += __shfl_down_sync(0xffffffffu, p0, off);
        p1 += __shfl_down_sync(0xffffffffu, p1, off);
    }
    if (j == 0) {
        float z0 = p0 + b2s[0];
        float z1 = p1 + b2s[1];
        float m = fmaxf(z0, z1);
        float lse = m + logf(expf(z0 - m) + expf(z1 - m));
        out[g * 2 + 0] = z0 - lse;
        out[g * 2 + 1] = z1 - lse;
    }
}

// ---------------------------------------------------------------------------
extern "C" void kernel_launch(void* const* d_in, const int* in_sizes, int n_in,
                              void* d_out, int out_size) {
    const float* x        = (const float*)d_in[0];
    const int*   ei       = (const int*)d_in[1];    // int32 (JAX x64 disabled)
    const int*   batch    = (const int*)d_in[2];
    const float* conv1_W1 = (const float*)d_in[3];
    const float* conv1_b1 = (const float*)d_in[4];
    const float* conv1_W2 = (const float*)d_in[5];
    const float* conv1_b2 = (const float*)d_in[6];
    const float* convs_W1 = (const float*)d_in[7];
    const float* convs_b1 = (const float*)d_in[8];
    const float* convs_W2 = (const float*)d_in[9];
    const float* convs_b2 = (const float*)d_in[10];
    const float* bn_gamma = (const float*)d_in[11];
    const float* bn_beta  = (const float*)d_in[12];
    const float* bn_mean  = (const float*)d_in[13];
    const float* bn_var   = (const float*)d_in[14];
    const float* fc1_W    = (const float*)d_in[15];
    const float* fc1_b    = (const float*)d_in[16];
    const float* fc2_W    = (const float*)d_in[17];
    const float* fc2_b    = (const float*)d_in[18];
    float* out = (float*)d_out;

    // prep + CSR build (by dst)
    prep_x<<<(N_NODES * 8 + 255) / 256, 256>>>(x);
    hist<<<(N_EDGES + 255) / 256, 256>>>(ei);
    scanA<<<NCHUNKS, SCAN_CHUNK>>>();
    scanB<<<1, 256>>>();
    scanC<<<(N_NODES + 255) / 256, 256>>>();
    place<<<(N_EDGES + 255) / 256, 256>>>(ei);

    const int LGRID = 148 * 4;   // persistent-ish: 4736 warps

    // layer 1: xp -> h0
    gin1<<<LGRID, 256>>>(conv1_W1, conv1_b1, conv1_W2, conv1_b2,
                         bn_gamma, bn_beta, bn_mean, bn_var);

    // layers 2..5: ping-pong h0 <-> h1 (ends in h0)
    const float* bufs_in[4]  = { d_h0, d_h1, d_h0, d_h1 };  // placeholders (resolved below)
    (void)bufs_in;
    float* hA = nullptr; float* hB = nullptr;
    cudaGetSymbolAddress((void**)&hA, d_h0);
    cudaGetSymbolAddress((void**)&hB, d_h1);

    for (int i = 0; i < 4; i++) {
        const float* hin = (i % 2 == 0) ? hA : hB;
        float* hout      = (i % 2 == 0) ? hB : hA;
        // layers write h1, h0, h1, h0 -> final in hA after swap fix:
        gin_layer<<<LGRID, 256>>>(hin, hout,
                                  convs_W1 + i * 32 * 32, convs_b1 + i * 32,
                                  convs_W2 + i * 32 * 32, convs_b2 + i * 32,
                                  bn_gamma + (i + 1) * 32, bn_beta + (i + 1) * 32,
                                  bn_mean + (i + 1) * 32,  bn_var + (i + 1) * 32);
    }
    // after 4 layers: h0->h1->h0->h1->h0  (i=0 in=h0 out=h1; i=1 in=h1 out=h0;
    //                 i=2 in=h0 out=h1; i=3 in=h1 out=h0) -> final in h0. OK.

    pool_scatter<<<(N_NODES * 8 + 255) / 256, 256>>>(batch);
    head<<<(N_GRAPHS + 7) / 8, 256>>>(fc1_W, fc1_b, fc2_W, fc2_b, out);
}

// round 4
// speedup vs baseline: 1.7930x; 1.7930x over previous
#include <cuda_runtime.h>

#define N_NODES  100000
#define N_EDGES  2000000
#define N_GRAPHS 1000
#define DIM      32
#define NF       7

#define SCAN_CHUNK 512
#define NCHUNKS ((N_NODES + SCAN_CHUNK - 1) / SCAN_CHUNK)   // 196

// ---- device scratch ----
__device__ __align__(16) float d_h0[N_NODES * DIM];
__device__ __align__(16) float d_h1[N_NODES * DIM];
__device__ __align__(16) float d_xp[N_NODES * 8];
__device__ __align__(16) float d_pool[N_GRAPHS * DIM];
__device__ int d_deg[N_NODES];
__device__ int d_incl[N_NODES];
__device__ int d_bsum[NCHUNKS];
__device__ int d_boff[NCHUNKS];
__device__ int d_off[N_NODES + 1];
__device__ int d_pos[N_NODES];
__device__ int d_csr[N_EDGES];

__device__ __forceinline__ float4 fma4(float s, float4 w, float4 a) {
    a.x = fmaf(s, w.x, a.x); a.y = fmaf(s, w.y, a.y);
    a.z = fmaf(s, w.z, a.z); a.w = fmaf(s, w.w, a.w);
    return a;
}
__device__ __forceinline__ float4 add4(float4 a, float4 b) {
    a.x += b.x; a.y += b.y; a.z += b.z; a.w += b.w; return a;
}
__device__ __forceinline__ float4 relu4(float4 a) {
    a.x = fmaxf(a.x, 0.f); a.y = fmaxf(a.y, 0.f);
    a.z = fmaxf(a.z, 0.f); a.w = fmaxf(a.w, 0.f); return a;
}

// ---------------------------------------------------------------------------
__global__ void prep_x(const float* __restrict__ x) {
    int i = blockIdx.x * blockDim.x + threadIdx.x;
    if (i < N_NODES * 8) {
        int n = i >> 3, j = i & 7;
        d_xp[i] = (j < NF) ? x[n * NF + j] : 0.0f;
        if (i < N_NODES) d_deg[i] = 0;
        if (i < N_GRAPHS * DIM) d_pool[i] = 0.0f;
    }
}

__global__ void hist(const int* __restrict__ ei) {
    int e = blockIdx.x * blockDim.x + threadIdx.x;
    if (e < N_EDGES) atomicAdd(&d_deg[ei[N_EDGES + e]], 1);
}

__global__ void scanA() {
    __shared__ int sh[SCAN_CHUNK];
    int i = blockIdx.x * SCAN_CHUNK + threadIdx.x;
    int v = (i < N_NODES) ? d_deg[i] : 0;
    sh[threadIdx.x] = v;
    __syncthreads();
#pragma unroll
    for (int off = 1; off < SCAN_CHUNK; off <<= 1) {
        int t = (threadIdx.x >= off) ? sh[threadIdx.x - off] : 0;
        __syncthreads();
        sh[threadIdx.x] += t;
        __syncthreads();
    }
    if (i < N_NODES) d_incl[i] = sh[threadIdx.x];
    if (threadIdx.x == SCAN_CHUNK - 1) d_bsum[blockIdx.x] = sh[threadIdx.x];
}

__global__ void scanB() {
    __shared__ int sh[256];
    int v = (threadIdx.x < NCHUNKS) ? d_bsum[threadIdx.x] : 0;
    sh[threadIdx.x] = v;
    __syncthreads();
#pragma unroll
    for (int off = 1; off < 256; off <<= 1) {
        int t = (threadIdx.x >= off) ? sh[threadIdx.x - off] : 0;
        __syncthreads();
        sh[threadIdx.x] += t;
        __syncthreads();
    }
    if (threadIdx.x < NCHUNKS) d_boff[threadIdx.x] = sh[threadIdx.x] - v;
}

__global__ void scanC() {
    int i = blockIdx.x * blockDim.x + threadIdx.x;
    if (i < N_NODES) {
        int excl = d_incl[i] - d_deg[i] + d_boff[i / SCAN_CHUNK];
        d_off[i] = excl;
        d_pos[i] = excl;
    }
    if (i == 0) d_off[N_NODES] = N_EDGES;
}

__global__ void place(const int* __restrict__ ei) {
    int e = blockIdx.x * blockDim.x + threadIdx.x;
    if (e < N_EDGES) {
        int s = ei[e], d = ei[N_EDGES + e];
        int p = atomicAdd(&d_pos[d], 1);
        d_csr[p] = s;
    }
}

// ---------------------------------------------------------------------------
// Layer 1 fused: 8 lanes per node. Lane q of a group owns output dims 4q..4q+3.
// z (8-dim) is scalar per lane. Grid is exactly N_NODES/32 blocks of 256.
__global__ void __launch_bounds__(256)
gin1(const float* __restrict__ W1, const float* __restrict__ b1,
     const float* __restrict__ W2, const float* __restrict__ b2,
     const float* __restrict__ gamma, const float* __restrict__ beta,
     const float* __restrict__ mean, const float* __restrict__ var) {
    __shared__ float4 sW1[NF * 8], sW2[32 * 8];
    __shared__ float4 sB1[8], sB2[8], sSC[8], sSH[8];
    int tid = threadIdx.x;
    if (tid < NF * 8) sW1[tid] = ((const float4*)W1)[tid];
    for (int i = tid; i < 32 * 8; i += 256) sW2[i] = ((const float4*)W2)[i];
    if (tid < 32) {
        if (tid < 8) {
            sB1[tid] = ((const float4*)b1)[tid];
            sB2[tid] = ((const float4*)b2)[tid];
        }
        float sc = gamma[tid] * rsqrtf(var[tid] + 1e-5f);
        float sh = beta[tid] - mean[tid] * sc;
        ((float*)sSC)[tid] = sc;
        ((float*)sSH)[tid] = sh;
    }
    __syncthreads();

    int q = tid & 7;
    int n = (blockIdx.x * 256 + tid) >> 3;   // exact: 3125*32 = 100000

    int beg = d_off[n], end = d_off[n + 1];
    float zq = d_xp[n * 8 + q];
    float zb = 0.0f;
    int e = beg;
    for (; e + 2 <= end; e += 2) {
        int s0 = d_csr[e], s1 = d_csr[e + 1];
        zq += d_xp[s0 * 8 + q];
        zb += d_xp[s1 * 8 + q];
    }
    if (e < end) zq += d_xp[d_csr[e] * 8 + q];
    zq += zb;

    // GEMV1: 7x32 (k over NF source dims, broadcast within 8-lane group)
    float4 acc = sB1[q];
#pragma unroll
    for (int k = 0; k < NF; k++) {
        float zk = __shfl_sync(0xffffffffu, zq, k, 8);
        acc = fma4(zk, sW1[k * 8 + q], acc);
    }
    acc = relu4(acc);

    // GEMV2: 32x32 — inputs are acc float4s across the 8 lanes
    float4 o = sB2[q];
#pragma unroll
    for (int kg = 0; kg < 8; kg++) {
        float ax = __shfl_sync(0xffffffffu, acc.x, kg, 8);
        float ay = __shfl_sync(0xffffffffu, acc.y, kg, 8);
        float az = __shfl_sync(0xffffffffu, acc.z, kg, 8);
        float aw = __shfl_sync(0xffffffffu, acc.w, kg, 8);
        o = fma4(ax, sW2[(kg * 4 + 0) * 8 + q], o);
        o = fma4(ay, sW2[(kg * 4 + 1) * 8 + q], o);
        o = fma4(az, sW2[(kg * 4 + 2) * 8 + q], o);
        o = fma4(aw, sW2[(kg * 4 + 3) * 8 + q], o);
    }
    o = relu4(o);

    float4 sc = sSC[q], sh = sSH[q];
    float4 r;
    r.x = fmaf(o.x, sc.x, sh.x); r.y = fmaf(o.y, sc.y, sh.y);
    r.z = fmaf(o.z, sc.z, sh.z); r.w = fmaf(o.w, sc.w, sh.w);
    ((float4*)d_h0)[n * 8 + q] = r;
}

// Layers 2..5 fused: 8 lanes/node, float4 per lane throughout.
__global__ void __launch_bounds__(256)
gin_layer(const float4* __restrict__ hin, float4* __restrict__ hout,
          const float* __restrict__ W1, const float* __restrict__ b1,
          const float* __restrict__ W2, const float* __restrict__ b2,
          const float* __restrict__ gamma, const float* __restrict__ beta,
          const float* __restrict__ mean, const float* __restrict__ var) {
    __shared__ float4 sW1[32 * 8], sW2[32 * 8];
    __shared__ float4 sB1[8], sB2[8], sSC[8], sSH[8];
    int tid = threadIdx.x;
    for (int i = tid; i < 32 * 8; i += 256) {
        sW1[i] = ((const float4*)W1)[i];
        sW2[i] = ((const float4*)W2)[i];
    }
    if (tid < 32) {
        if (tid < 8) {
            sB1[tid] = ((const float4*)b1)[tid];
            sB2[tid] = ((const float4*)b2)[tid];
        }
        float sc = gamma[tid] * rsqrtf(var[tid] + 1e-5f);
        float sh = beta[tid] - mean[tid] * sc;
        ((float*)sSC)[tid] = sc;
        ((float*)sSH)[tid] = sh;
    }
    __syncthreads();

    int q = tid & 7;
    int n = (blockIdx.x * 256 + tid) >> 3;

    int beg = d_off[n], end = d_off[n + 1];
    float4 z = hin[n * 8 + q];
    float4 z2 = make_float4(0.f, 0.f, 0.f, 0.f);
    int e = beg;
    for (; e + 2 <= end; e += 2) {
        int s0 = d_csr[e], s1 = d_csr[e + 1];
        z  = add4(z,  hin[s0 * 8 + q]);
        z2 = add4(z2, hin[s1 * 8 + q]);
    }
    if (e < end) z = add4(z, hin[d_csr[e] * 8 + q]);
    z = add4(z, z2);

    // GEMV1
    float4 a = sB1[q];
#pragma unroll
    for (int kg = 0; kg < 8; kg++) {
        float zx = __shfl_sync(0xffffffffu, z.x, kg, 8);
        float zy = __shfl_sync(0xffffffffu, z.y, kg, 8);
        float zz = __shfl_sync(0xffffffffu, z.z, kg, 8);
        float zw = __shfl_sync(0xffffffffu, z.w, kg, 8);
        a = fma4(zx, sW1[(kg * 4 + 0) * 8 + q], a);
        a = fma4(zy, sW1[(kg * 4 + 1) * 8 + q], a);
        a = fma4(zz, sW1[(kg * 4 + 2) * 8 + q], a);
        a = fma4(zw, sW1[(kg * 4 + 3) * 8 + q], a);
    }
    a = relu4(a);

    // GEMV2
    float4 o = sB2[q];
#pragma unroll
    for (int kg = 0; kg < 8; kg++) {
        float ax = __shfl_sync(0xffffffffu, a.x, kg, 8);
        float ay = __shfl_sync(0xffffffffu, a.y, kg, 8);
        float az = __shfl_sync(0xffffffffu, a.z, kg, 8);
        float aw = __shfl_sync(0xffffffffu, a.w, kg, 8);
        o = fma4(ax, sW2[(kg * 4 + 0) * 8 + q], o);
        o = fma4(ay, sW2[(kg * 4 + 1) * 8 + q], o);
        o = fma4(az, sW2[(kg * 4 + 2) * 8 + q], o);
        o = fma4(aw, sW2[(kg * 4 + 3) * 8 + q], o);
    }
    o = relu4(o);

    float4 sc = sSC[q], sh = sSH[q];
    float4 r;
    r.x = fmaf(o.x, sc.x, sh.x); r.y = fmaf(o.y, sc.y, sh.y);
    r.z = fmaf(o.z, sc.z, sh.z); r.w = fmaf(o.w, sc.w, sh.w);
    hout[n * 8 + q] = r;
}

// ---------------------------------------------------------------------------
__device__ __forceinline__ void red_add_v4(float* a, float4 v) {
    asm volatile("red.global.add.v4.f32 [%0], {%1,%2,%3,%4};"
                 :: "l"(a), "f"(v.x), "f"(v.y), "f"(v.z), "f"(v.w)
                 : "memory");
}

__global__ void pool_scatter(const int* __restrict__ batch) {
    int t = blockIdx.x * blockDim.x + threadIdx.x;
    if (t >= N_NODES * 8) return;
    int n = t >> 3, p = t & 7;
    int g = batch[n];
    float4 v = *reinterpret_cast<const float4*>(&d_h0[n * DIM + p * 4]);
    red_add_v4(&d_pool[g * DIM + p * 4], v);
}

__global__ void head(const float* __restrict__ fc1W, const float* __restrict__ fc1b,
                     const float* __restrict__ fc2W, const float* __restrict__ fc2b,
                     float* __restrict__ out) {
    __shared__ float W1s[32 * 32], W2s[64], b1s[32], b2s[2];
    int tid = threadIdx.x;
    for (int i = tid; i < 32 * 32; i += blockDim.x) W1s[i] = fc1W[i];
    if (tid < 64) W2s[tid] = fc2W[tid];
    if (tid < 32) b1s[tid] = fc1b[tid];
    if (tid < 2)  b2s[tid] = fc2b[tid];
    __syncthreads();

    int warp = tid >> 5, j = tid & 31;
    int g = blockIdx.x * (blockDim.x >> 5) + warp;
    if (g >= N_GRAPHS) return;

    float gj = d_pool[g * DIM + j];
    float a = b1s[j];
#pragma unroll
    for (int k = 0; k < 32; k++)
        a = fmaf(__shfl_sync(0xffffffffu, gj, k), W1s[k * 32 + j], a);
    a = fmaxf(a, 0.0f);

    float p0 = a * W2s[j * 2 + 0];
    float p1 = a * W2s[j * 2 + 1];
#pragma unroll
    for (int off = 16; off > 0; off >>= 1) {
        p0 += __shfl_down_sync(0xffffffffu, p0, off);
        p1 += __shfl_down_sync(0xffffffffu, p1, off);
    }
    if (j == 0) {
        float z0 = p0 + b2s[0];
        float z1 = p1 + b2s[1];
        float m = fmaxf(z0, z1);
        float lse = m + logf(expf(z0 - m) + expf(z1 - m));
        out[g * 2 + 0] = z0 - lse;
        out[g * 2 + 1] = z1 - lse;
    }
}

// ---------------------------------------------------------------------------
extern "C" void kernel_launch(void* const* d_in, const int* in_sizes, int n_in,
                              void* d_out, int out_size) {
    const float* x        = (const float*)d_in[0];
    const int*   ei       = (const int*)d_in[1];
    const int*   batch    = (const int*)d_in[2];
    const float* conv1_W1 = (const float*)d_in[3];
    const float* conv1_b1 = (const float*)d_in[4];
    const float* conv1_W2 = (const float*)d_in[5];
    const float* conv1_b2 = (const float*)d_in[6];
    const float* convs_W1 = (const float*)d_in[7];
    const float* convs_b1 = (const float*)d_in[8];
    const float* convs_W2 = (const float*)d_in[9];
    const float* convs_b2 = (const float*)d_in[10];
    const float* bn_gamma = (const float*)d_in[11];
    const float* bn_beta  = (const float*)d_in[12];
    const float* bn_mean  = (const float*)d_in[13];
    const float* bn_var   = (const float*)d_in[14];
    const float* fc1_W    = (const float*)d_in[15];
    const float* fc1_b    = (const float*)d_in[16];
    const float* fc2_W    = (const float*)d_in[17];
    const float* fc2_b    = (const float*)d_in[18];
    float* out = (float*)d_out;

    // prep + CSR build (by dst)
    prep_x<<<(N_NODES * 8 + 255) / 256, 256>>>(x);
    hist<<<(N_EDGES + 255) / 256, 256>>>(ei);
    scanA<<<NCHUNKS, SCAN_CHUNK>>>();
    scanB<<<1, 256>>>();
    scanC<<<(N_NODES + 255) / 256, 256>>>();
    place<<<(N_EDGES + 255) / 256, 256>>>(ei);

    float* hA = nullptr; float* hB = nullptr;
    cudaGetSymbolAddress((void**)&hA, d_h0);
    cudaGetSymbolAddress((void**)&hB, d_h1);

    const int NBLK = N_NODES * 8 / 256;   // 3125, exact

    gin1<<<NBLK, 256>>>(conv1_W1, conv1_b1, conv1_W2, conv1_b2,
                        bn_gamma, bn_beta, bn_mean, bn_var);

    for (int i = 0; i < 4; i++) {
        const float4* hin = (const float4*)((i % 2 == 0) ? hA : hB);
        float4* hout      = (float4*)((i % 2 == 0) ? hB : hA);
        gin_layer<<<NBLK, 256>>>(hin, hout,
                                 convs_W1 + i * 32 * 32, convs_b1 + i * 32,
                                 convs_W2 + i * 32 * 32, convs_b2 + i * 32,
                                 bn_gamma + (i + 1) * 32, bn_beta + (i + 1) * 32,
                                 bn_mean + (i + 1) * 32,  bn_var + (i + 1) * 32);
    }
    // ping-pong ends in d_h0

    pool_scatter<<<(N_NODES * 8 + 255) / 256, 256>>>(batch);
    head<<<(N_GRAPHS + 7) / 8, 256>>>(fc1_W, fc1_b, fc2_W, fc2_b, out);
}

// round 5
// speedup vs baseline: 1.8661x; 1.0408x over previous
#include <cuda_runtime.h>

#define N_NODES  100000
#define N_EDGES  2000000
#define N_GRAPHS 1000
#define DIM      32
#define NF       7

// ---- device scratch ----
__device__ __align__(16) float d_h0[N_NODES * DIM];
__device__ __align__(16) float d_h1[N_NODES * DIM];
__device__ __align__(16) float d_xp[N_NODES * 8];
__device__ __align__(16) float d_pool[N_GRAPHS * DIM];
__device__ int d_deg[N_NODES];
__device__ int d_off[N_NODES];
__device__ int d_pos[N_NODES];
__device__ int d_csr[N_EDGES];
__device__ int d_ctr;

__device__ __forceinline__ float4 fma4(float s, float4 w, float4 a) {
    a.x = fmaf(s, w.x, a.x); a.y = fmaf(s, w.y, a.y);
    a.z = fmaf(s, w.z, a.z); a.w = fmaf(s, w.w, a.w);
    return a;
}
__device__ __forceinline__ float4 add4(float4 a, float4 b) {
    a.x += b.x; a.y += b.y; a.z += b.z; a.w += b.w; return a;
}
__device__ __forceinline__ float4 relu4(float4 a) {
    a.x = fmaxf(a.x, 0.f); a.y = fmaxf(a.y, 0.f);
    a.z = fmaxf(a.z, 0.f); a.w = fmaxf(a.w, 0.f); return a;
}
__device__ __forceinline__ void red_add_v4(float* a, float4 v) {
    asm volatile("red.global.add.v4.f32 [%0], {%1,%2,%3,%4};"
                 :: "l"(a), "f"(v.x), "f"(v.y), "f"(v.z), "f"(v.w)
                 : "memory");
}

// ---------------------------------------------------------------------------
// prep: pad x -> xp, zero deg/pool/ctr
__global__ void prep_x(const float* __restrict__ x) {
    int i = blockIdx.x * blockDim.x + threadIdx.x;
    if (i < N_NODES * 8) {
        int n = i >> 3, j = i & 7;
        d_xp[i] = (j < NF) ? x[n * NF + j] : 0.0f;
        if (i < N_NODES) d_deg[i] = 0;
        if (i < N_GRAPHS * DIM) d_pool[i] = 0.0f;
        if (i == 0) d_ctr = 0;
    }
}

__global__ void hist(const int* __restrict__ ei) {
    int e = blockIdx.x * blockDim.x + threadIdx.x;
    if (e < N_EDGES) atomicAdd(&d_deg[ei[N_EDGES + e]], 1);
}

// atomic row-base assignment (replaces prefix scan; layout nondeterministic,
// but CSR row order already is, and sums are tolerance-checked)
__global__ void offsets() {
    int n = blockIdx.x * blockDim.x + threadIdx.x;
    if (n < N_NODES) {
        int base = atomicAdd(&d_ctr, d_deg[n]);
        d_off[n] = base;
        d_pos[n] = base;
    }
}

__global__ void place(const int* __restrict__ ei) {
    int e = blockIdx.x * blockDim.x + threadIdx.x;
    if (e < N_EDGES) {
        int s = ei[e], d = ei[N_EDGES + e];
        int p = atomicAdd(&d_pos[d], 1);
        d_csr[p] = s;
    }
}

// ---------------------------------------------------------------------------
// Layer 1 fused: 8 lanes per node; lane q owns output dims 4q..4q+3.
__global__ void __launch_bounds__(256)
gin1(const float* __restrict__ W1, const float* __restrict__ b1,
     const float* __restrict__ W2, const float* __restrict__ b2,
     const float* __restrict__ gamma, const float* __restrict__ beta,
     const float* __restrict__ mean, const float* __restrict__ var) {
    __shared__ float4 sW1[NF * 8], sW2[32 * 8];
    __shared__ float4 sB1[8], sB2[8], sSC[8], sSH[8];
    int tid = threadIdx.x;
    if (tid < NF * 8) sW1[tid] = ((const float4*)W1)[tid];
    for (int i = tid; i < 32 * 8; i += 256) sW2[i] = ((const float4*)W2)[i];
    if (tid < 32) {
        if (tid < 8) {
            sB1[tid] = ((const float4*)b1)[tid];
            sB2[tid] = ((const float4*)b2)[tid];
        }
        float sc = gamma[tid] * rsqrtf(var[tid] + 1e-5f);
        float sh = beta[tid] - mean[tid] * sc;
        ((float*)sSC)[tid] = sc;
        ((float*)sSH)[tid] = sh;
    }
    __syncthreads();

    int q = tid & 7;
    int n = (blockIdx.x * 256 + tid) >> 3;   // exact: 3125*32 = 100000

    int beg = d_off[n], end = beg + d_deg[n];
    float zq = d_xp[n * 8 + q];
    float zb = 0.0f;
    int e = beg;
    for (; e + 2 <= end; e += 2) {
        int s0 = d_csr[e], s1 = d_csr[e + 1];
        zq += d_xp[s0 * 8 + q];
        zb += d_xp[s1 * 8 + q];
    }
    if (e < end) zq += d_xp[d_csr[e] * 8 + q];
    zq += zb;

    float4 acc = sB1[q];
#pragma unroll
    for (int k = 0; k < NF; k++) {
        float zk = __shfl_sync(0xffffffffu, zq, k, 8);
        acc = fma4(zk, sW1[k * 8 + q], acc);
    }
    acc = relu4(acc);

    float4 o = sB2[q];
#pragma unroll
    for (int kg = 0; kg < 8; kg++) {
        float ax = __shfl_sync(0xffffffffu, acc.x, kg, 8);
        float ay = __shfl_sync(0xffffffffu, acc.y, kg, 8);
        float az = __shfl_sync(0xffffffffu, acc.z, kg, 8);
        float aw = __shfl_sync(0xffffffffu, acc.w, kg, 8);
        o = fma4(ax, sW2[(kg * 4 + 0) * 8 + q], o);
        o = fma4(ay, sW2[(kg * 4 + 1) * 8 + q], o);
        o = fma4(az, sW2[(kg * 4 + 2) * 8 + q], o);
        o = fma4(aw, sW2[(kg * 4 + 3) * 8 + q], o);
    }
    o = relu4(o);

    float4 sc = sSC[q], sh = sSH[q];
    float4 r;
    r.x = fmaf(o.x, sc.x, sh.x); r.y = fmaf(o.y, sc.y, sh.y);
    r.z = fmaf(o.z, sc.z, sh.z); r.w = fmaf(o.w, sc.w, sh.w);
    ((float4*)d_h0)[n * 8 + q] = r;
}

// Layers 2..5 fused. POOL=1 on the last layer: emit red.v4 into d_pool
// instead of storing h (fuses global add pool).
template <int POOL>
__global__ void __launch_bounds__(256)
gin_layer(const float4* __restrict__ hin, float4* __restrict__ hout,
          const int* __restrict__ batch,
          const float* __restrict__ W1, const float* __restrict__ b1,
          const float* __restrict__ W2, const float* __restrict__ b2,
          const float* __restrict__ gamma, const float* __restrict__ beta,
          const float* __restrict__ mean, const float* __restrict__ var) {
    __shared__ float4 sW1[32 * 8], sW2[32 * 8];
    __shared__ float4 sB1[8], sB2[8], sSC[8], sSH[8];
    int tid = threadIdx.x;
    for (int i = tid; i < 32 * 8; i += 256) {
        sW1[i] = ((const float4*)W1)[i];
        sW2[i] = ((const float4*)W2)[i];
    }
    if (tid < 32) {
        if (tid < 8) {
            sB1[tid] = ((const float4*)b1)[tid];
            sB2[tid] = ((const float4*)b2)[tid];
        }
        float sc = gamma[tid] * rsqrtf(var[tid] + 1e-5f);
        float sh = beta[tid] - mean[tid] * sc;
        ((float*)sSC)[tid] = sc;
        ((float*)sSH)[tid] = sh;
    }
    __syncthreads();

    int q = tid & 7;
    int n = (blockIdx.x * 256 + tid) >> 3;

    int beg = d_off[n], end = beg + d_deg[n];
    float4 z = hin[n * 8 + q];
    float4 z1 = make_float4(0.f, 0.f, 0.f, 0.f);
    float4 z2 = make_float4(0.f, 0.f, 0.f, 0.f);
    float4 z3 = make_float4(0.f, 0.f, 0.f, 0.f);
    int e = beg;
    for (; e + 4 <= end; e += 4) {
        int s0 = d_csr[e], s1 = d_csr[e + 1], s2 = d_csr[e + 2], s3 = d_csr[e + 3];
        z  = add4(z,  hin[s0 * 8 + q]);
        z1 = add4(z1, hin[s1 * 8 + q]);
        z2 = add4(z2, hin[s2 * 8 + q]);
        z3 = add4(z3, hin[s3 * 8 + q]);
    }
    for (; e < end; e++) z = add4(z, hin[d_csr[e] * 8 + q]);
    z = add4(add4(z, z1), add4(z2, z3));

    // GEMV1
    float4 a = sB1[q];
#pragma unroll
    for (int kg = 0; kg < 8; kg++) {
        float zx = __shfl_sync(0xffffffffu, z.x, kg, 8);
        float zy = __shfl_sync(0xffffffffu, z.y, kg, 8);
        float zz = __shfl_sync(0xffffffffu, z.z, kg, 8);
        float zw = __shfl_sync(0xffffffffu, z.w, kg, 8);
        a = fma4(zx, sW1[(kg * 4 + 0) * 8 + q], a);
        a = fma4(zy, sW1[(kg * 4 + 1) * 8 + q], a);
        a = fma4(zz, sW1[(kg * 4 + 2) * 8 + q], a);
        a = fma4(zw, sW1[(kg * 4 + 3) * 8 + q], a);
    }
    a = relu4(a);

    // GEMV2
    float4 o = sB2[q];
#pragma unroll
    for (int kg = 0; kg < 8; kg++) {
        float ax = __shfl_sync(0xffffffffu, a.x, kg, 8);
        float ay = __shfl_sync(0xffffffffu, a.y, kg, 8);
        float az = __shfl_sync(0xffffffffu, a.z, kg, 8);
        float aw = __shfl_sync(0xffffffffu, a.w, kg, 8);
        o = fma4(ax, sW2[(kg * 4 + 0) * 8 + q], o);
        o = fma4(ay, sW2[(kg * 4 + 1) * 8 + q], o);
        o = fma4(az, sW2[(kg * 4 + 2) * 8 + q], o);
        o = fma4(aw, sW2[(kg * 4 + 3) * 8 + q], o);
    }
    o = relu4(o);

    float4 sc = sSC[q], sh = sSH[q];
    float4 r;
    r.x = fmaf(o.x, sc.x, sh.x); r.y = fmaf(o.y, sc.y, sh.y);
    r.z = fmaf(o.z, sc.z, sh.z); r.w = fmaf(o.w, sc.w, sh.w);

    if (POOL) {
        int g = batch[n];
        red_add_v4(&d_pool[g * DIM + q * 4], r);
    } else {
        hout[n * 8 + q] = r;
    }
}

// head: fc1 + relu + fc2 + log_softmax; one warp per graph
__global__ void head(const float* __restrict__ fc1W, const float* __restrict__ fc1b,
                     const float* __restrict__ fc2W, const float* __restrict__ fc2b,
                     float* __restrict__ out) {
    __shared__ float W1s[32 * 32], W2s[64], b1s[32], b2s[2];
    int tid = threadIdx.x;
    for (int i = tid; i < 32 * 32; i += blockDim.x) W1s[i] = fc1W[i];
    if (tid < 64) W2s[tid] = fc2W[tid];
    if (tid < 32) b1s[tid] = fc1b[tid];
    if (tid < 2)  b2s[tid] = fc2b[tid];
    __syncthreads();

    int warp = tid >> 5, j = tid & 31;
    int g = blockIdx.x * (blockDim.x >> 5) + warp;
    if (g >= N_GRAPHS) return;

    float gj = d_pool[g * DIM + j];
    float a = b1s[j];
#pragma unroll
    for (int k = 0; k < 32; k++)
        a = fmaf(__shfl_sync(0xffffffffu, gj, k), W1s[k * 32 + j], a);
    a = fmaxf(a, 0.0f);

    float p0 = a * W2s[j * 2 + 0];
    float p1 = a * W2s[j * 2 + 1];
#pragma unroll
    for (int off = 16; off > 0; off >>= 1) {
        p0 += __shfl_down_sync(0xffffffffu, p0, off);
        p1 += __shfl_down_sync(0xffffffffu, p1, off);
    }
    if (j == 0) {
        float z0 = p0 + b2s[0];
        float z1 = p1 + b2s[1];
        float m = fmaxf(z0, z1);
        float lse = m + logf(expf(z0 - m) + expf(z1 - m));
        out[g * 2 + 0] = z0 - lse;
        out[g * 2 + 1] = z1 - lse;
    }
}

// ---------------------------------------------------------------------------
extern "C" void kernel_launch(void* const* d_in, const int* in_sizes, int n_in,
                              void* d_out, int out_size) {
    const float* x        = (const float*)d_in[0];
    const int*   ei       = (const int*)d_in[1];
    const int*   batch    = (const int*)d_in[2];
    const float* conv1_W1 = (const float*)d_in[3];
    const float* conv1_b1 = (const float*)d_in[4];
    const float* conv1_W2 = (const float*)d_in[5];
    const float* conv1_b2 = (const float*)d_in[6];
    const float* convs_W1 = (const float*)d_in[7];
    const float* convs_b1 = (const float*)d_in[8];
    const float* convs_W2 = (const float*)d_in[9];
    const float* convs_b2 = (const float*)d_in[10];
    const float* bn_gamma = (const float*)d_in[11];
    const float* bn_beta  = (const float*)d_in[12];
    const float* bn_mean  = (const float*)d_in[13];
    const float* bn_var   = (const float*)d_in[14];
    const float* fc1_W    = (const float*)d_in[15];
    const float* fc1_b    = (const float*)d_in[16];
    const float* fc2_W    = (const float*)d_in[17];
    const float* fc2_b    = (const float*)d_in[18];
    float* out = (float*)d_out;

    // prep + CSR build (by dst)
    prep_x<<<(N_NODES * 8 + 255) / 256, 256>>>(x);
    hist<<<(N_EDGES + 255) / 256, 256>>>(ei);
    offsets<<<(N_NODES + 255) / 256, 256>>>();
    place<<<(N_EDGES + 255) / 256, 256>>>(ei);

    float* hA = nullptr; float* hB = nullptr;
    cudaGetSymbolAddress((void**)&hA, d_h0);
    cudaGetSymbolAddress((void**)&hB, d_h1);

    const int NBLK = N_NODES * 8 / 256;   // 3125, exact

    // layer 1: xp -> h0
    gin1<<<NBLK, 256>>>(conv1_W1, conv1_b1, conv1_W2, conv1_b2,
                        bn_gamma, bn_beta, bn_mean, bn_var);

    // layers 2..4: ping-pong h0 -> h1 -> h0 -> h1
    for (int i = 0; i < 3; i++) {
        const float4* hin = (const float4*)((i % 2 == 0) ? hA : hB);
        float4* hout      = (float4*)((i % 2 == 0) ? hB : hA);
        gin_layer<0><<<NBLK, 256>>>(hin, hout, batch,
                                    convs_W1 + i * 32 * 32, convs_b1 + i * 32,
                                    convs_W2 + i * 32 * 32, convs_b2 + i * 32,
                                    bn_gamma + (i + 1) * 32, bn_beta + (i + 1) * 32,
                                    bn_mean + (i + 1) * 32,  bn_var + (i + 1) * 32);
    }

    // layer 5 (i=3): input is h1, output pooled directly into d_pool
    gin_layer<1><<<NBLK, 256>>>((const float4*)hB, nullptr, batch,
                                convs_W1 + 3 * 32 * 32, convs_b1 + 3 * 32,
                                convs_W2 + 3 * 32 * 32, convs_b2 + 3 * 32,
                                bn_gamma + 4 * 32, bn_beta + 4 * 32,
                                bn_mean + 4 * 32,  bn_var + 4 * 32);

    head<<<(N_GRAPHS + 7) / 8, 256>>>(fc1_W, fc1_b, fc2_W, fc2_b, out);
}